// round 16
// baseline (speedup 1.0000x reference)
#include <cuda_runtime.h>
#include <cuda.h>

typedef unsigned long long ull;

// out = (w1+w2)*s + (w3-w2)*G3(s) + (w4-w3)*G5(s) - w4*G7(s)
// R15 structure (tile 128x64, NTH=128, 5-slice TMA fill + per-warp waits,
// streaming stores) with the horizontal pass ALSO packed f32x2:
// 9 column-pair packs + 6 add2 + 18 fma2 per 4 cols (vs 48 scalar slots).
// Vertical: transposed-FIR f32x2 ring (unchanged). 5 CTAs/SM.

#define IMG 512
#define TX 128
#define TY 64
#define NTH 128
#define SW 136            // TX + 8 (left halo 4, right halo 4)
#define SH 70             // TY + 6
#define NF4 (SW / 4)
#define STEPS 22
#define SAROWS 16         // slices 0..3
#define SBROWS 6          // slice 4
#define SABYTES (SAROWS * SW * 4)   // 8704
#define SBBYTES (SBROWS * SW * 4)   // 3264

#define K3_0 0.5220116f
#define K3_1 0.2389942f
#define K5_0 0.3695467f
#define K5_1 0.2444604f
#define K5_2 0.0707663f
#define K7_0 0.2880262f
#define K7_1 0.2231734f
#define K7_2 0.1038183f
#define K7_3 0.0289952f

__device__ __forceinline__ ull pk2(float lo, float hi) {
    ull r; asm("mov.b64 %0, {%1, %2};" : "=l"(r) : "f"(lo), "f"(hi)); return r;
}
__device__ __forceinline__ ull bcast2(float x) {          // compile-time literal
    unsigned u = __float_as_uint(x);
    return ((ull)u << 32) | (ull)u;
}
__device__ __forceinline__ ull add2(ull a, ull b) {
    ull r; asm("add.rn.f32x2 %0, %1, %2;" : "=l"(r) : "l"(a), "l"(b)); return r;
}
__device__ __forceinline__ ull mul2(ull a, ull b) {
    ull r; asm("mul.rn.f32x2 %0, %1, %2;" : "=l"(r) : "l"(a), "l"(b)); return r;
}
__device__ __forceinline__ ull fma2(ull a, ull b, ull c) {
    ull r; asm("fma.rn.f32x2 %0, %1, %2, %3;" : "=l"(r) : "l"(a), "l"(b), "l"(c)); return r;
}
__device__ __forceinline__ unsigned smem_u32(const void* p) {
    unsigned r;
    asm("{ .reg .u64 t; cvta.to.shared.u64 t, %1; cvt.u32.u64 %0, t; }" : "=r"(r) : "l"(p));
    return r;
}
__device__ __forceinline__ void mbar_wait(unsigned mb, unsigned parity) {
    unsigned done;
    asm volatile(
        "{\n\t.reg .pred p;\n\t"
        "mbarrier.try_wait.parity.acquire.cta.shared::cta.b64 p, [%1], %2;\n\t"
        "selp.b32 %0, 1, 0, p;\n\t}"
        : "=r"(done) : "r"(mb), "r"(parity) : "memory");
    if (!done) {
        asm volatile(
            "{\n\t.reg .pred P1;\n\t"
            "W%=:\n\t"
            "mbarrier.try_wait.parity.acquire.cta.shared::cta.b64 P1, [%0], %1, 0x989680;\n\t"
            "@P1 bra.uni D%=;\n\t"
            "bra.uni W%=;\n\t"
            "D%=:\n\t}"
            :: "r"(mb), "r"(parity) : "memory");
    }
}

// ---- compute body: packed horizontal (f32x2) + f32x2 ring vertical ----
__device__ __forceinline__ void compute_tile(
    float (&tile)[SH][SW],
    const float* __restrict__ w1p, const float* __restrict__ w2p,
    const float* __restrict__ w3p, const float* __restrict__ w4p,
    float* __restrict__ op, int tileX, int tileY)
{
    const int tid = threadIdx.x;
    const float W1 = *w1p, W2 = *w2p, W3 = *w3p, W4 = *w4p;
    const float cA = W1 + W2, cB = W3 - W2, cC = W4 - W3, cD = -W4;
    // vertical (weight-folded, runtime) constants
    const ull cAp = pk2(cA, cA);
    const ull a30 = pk2(cB * K3_0, cB * K3_0);
    const ull a31 = pk2(cB * K3_1, cB * K3_1);
    const ull a50 = pk2(cC * K5_0, cC * K5_0);
    const ull a51 = pk2(cC * K5_1, cC * K5_1);
    const ull a52 = pk2(cC * K5_2, cC * K5_2);
    const ull a70 = pk2(cD * K7_0, cD * K7_0);
    const ull a71 = pk2(cD * K7_1, cD * K7_1);
    const ull a72 = pk2(cD * K7_2, cD * K7_2);
    const ull a73 = pk2(cD * K7_3, cD * K7_3);
    // horizontal (raw, compile-time literal broadcast) constants
    const ull k30 = bcast2(K3_0), k31 = bcast2(K3_1);
    const ull k50 = bcast2(K5_0), k51 = bcast2(K5_1), k52 = bcast2(K5_2);
    const ull k70 = bcast2(K7_0), k71 = bcast2(K7_1), k72 = bcast2(K7_2),
              k73 = bcast2(K7_3);

    const int xg = tid & 31;            // 32 col-groups of 4 cols
    const int rg = tid >> 5;            // 4 row-groups (== warp id)
    const int cb = 4 * xg;              // first float4; centers cb+4..cb+7
    const int rowBase = rg * 16;
    float* orow = op + (size_t)(tileY + rowBase) * IMG + tileX + 4 * xg;

    ull acc[7][2];

    #pragma unroll
    for (int k = 0; k < STEPS; k++) {
        const int sr = rowBase + k;

        float4 A  = *reinterpret_cast<const float4*>(&tile[sr][cb]);
        float4 Bv = *reinterpret_cast<const float4*>(&tile[sr][cb + 4]);
        float4 C  = *reinterpret_cast<const float4*>(&tile[sr][cb + 8]);

        // column pairs (x1..x10 -> 9 overlapping f32x2 pairs)
        ull P12 = pk2(A.y,  A.z);
        ull P23 = pk2(A.z,  A.w);
        ull P34 = pk2(A.w,  Bv.x);
        ull P45 = pk2(Bv.x, Bv.y);
        ull P56 = pk2(Bv.y, Bv.z);
        ull P67 = pk2(Bv.z, Bv.w);
        ull P78 = pk2(Bv.w, C.x);
        ull P89 = pk2(C.x,  C.y);
        ull P9A = pk2(C.y,  C.z);

        // symmetric tap sums, lane a = cols (0,1), lane b = cols (2,3)
        ull p1a = add2(P34, P56), p2a = add2(P23, P67), p3a = add2(P12, P78);
        ull p1b = add2(P56, P78), p2b = add2(P45, P89), p3b = add2(P34, P9A);

        ull t3a = fma2(k31, p1a, mul2(k30, P45));
        ull t5a = fma2(k52, p2a, fma2(k51, p1a, mul2(k50, P45)));
        ull t7a = fma2(k73, p3a, fma2(k72, p2a, fma2(k71, p1a, mul2(k70, P45))));
        ull t3b = fma2(k31, p1b, mul2(k30, P67));
        ull t5b = fma2(k52, p2b, fma2(k51, p1b, mul2(k50, P67)));
        ull t7b = fma2(k73, p3b, fma2(k72, p2b, fma2(k71, p1b, mul2(k70, P67))));
        ull rwa = P45, rwb = P67;

        if (k <= 15) {                                   // d=0 init
            acc[k % 7][0] = mul2(a73, t7a);
            acc[k % 7][1] = mul2(a73, t7b);
        }
        if (k >= 1 && k <= 16) {                         // d=1
            ull u = acc[(k - 1) % 7][0], v = acc[(k - 1) % 7][1];
            u = fma2(a72, t7a, u);  v = fma2(a72, t7b, v);
            u = fma2(a52, t5a, u);  v = fma2(a52, t5b, v);
            acc[(k - 1) % 7][0] = u; acc[(k - 1) % 7][1] = v;
        }
        if (k >= 2 && k <= 17) {                         // d=2
            ull u = acc[(k - 2) % 7][0], v = acc[(k - 2) % 7][1];
            u = fma2(a71, t7a, u);  v = fma2(a71, t7b, v);
            u = fma2(a51, t5a, u);  v = fma2(a51, t5b, v);
            u = fma2(a31, t3a, u);  v = fma2(a31, t3b, v);
            acc[(k - 2) % 7][0] = u; acc[(k - 2) % 7][1] = v;
        }
        if (k >= 3 && k <= 18) {                         // d=3 (center)
            ull u = acc[(k - 3) % 7][0], v = acc[(k - 3) % 7][1];
            u = fma2(a70, t7a, u);  v = fma2(a70, t7b, v);
            u = fma2(a50, t5a, u);  v = fma2(a50, t5b, v);
            u = fma2(a30, t3a, u);  v = fma2(a30, t3b, v);
            u = fma2(cAp, rwa, u);  v = fma2(cAp, rwb, v);
            acc[(k - 3) % 7][0] = u; acc[(k - 3) % 7][1] = v;
        }
        if (k >= 4 && k <= 19) {                         // d=4
            ull u = acc[(k - 4) % 7][0], v = acc[(k - 4) % 7][1];
            u = fma2(a71, t7a, u);  v = fma2(a71, t7b, v);
            u = fma2(a51, t5a, u);  v = fma2(a51, t5b, v);
            u = fma2(a31, t3a, u);  v = fma2(a31, t3b, v);
            acc[(k - 4) % 7][0] = u; acc[(k - 4) % 7][1] = v;
        }
        if (k >= 5 && k <= 20) {                         // d=5
            ull u = acc[(k - 5) % 7][0], v = acc[(k - 5) % 7][1];
            u = fma2(a72, t7a, u);  v = fma2(a72, t7b, v);
            u = fma2(a52, t5a, u);  v = fma2(a52, t5b, v);
            acc[(k - 5) % 7][0] = u; acc[(k - 5) % 7][1] = v;
        }
        if (k >= 6) {                                    // d=6: finish + streaming STG.128
            ull ox = fma2(a73, t7a, acc[(k - 6) % 7][0]);
            ull oy = fma2(a73, t7b, acc[(k - 6) % 7][1]);
            asm volatile("st.global.cs.v2.u64 [%0], {%1, %2};"
                         :: "l"(orow + (size_t)(k - 6) * IMG), "l"(ox), "l"(oy)
                         : "memory");
        }
    }
}

// ---- TMA kernel: 5-slice fill (rows {0,16,32,48,64}), per-warp waits ----
__global__ void __launch_bounds__(NTH, 5)
mgdf_tma_kernel(const __grid_constant__ CUtensorMap tmapA,   // box SW x 16
                const __grid_constant__ CUtensorMap tmapB,   // box SW x 6
                const float* __restrict__ w1p, const float* __restrict__ w2p,
                const float* __restrict__ w3p, const float* __restrict__ w4p,
                float* __restrict__ out)
{
    __shared__ __align__(128) float tile[SH][SW];
    __shared__ __align__(8) ull mbar[5];

    const int tid = threadIdx.x;
    const int wid = tid >> 5;           // == row-group 0..3
    const int tileX = blockIdx.x * TX;
    const int tileY = blockIdx.y * TY;
    const int img = blockIdx.z;
    float* op = out + (size_t)img * (IMG * IMG);

    const unsigned mb0 = smem_u32(&mbar[0]);
    if (tid < 5) {
        asm volatile("mbarrier.init.shared.b64 [%0], 1;"
                     :: "r"(mb0 + 8u * tid) : "memory");
    }
    __syncthreads();

    if (tid == 0) {
        // Slices at rows {0,16,32,48,64}: all offsets 128B-aligned (row%4==0).
        #pragma unroll
        for (int q = 0; q < 5; q++) {
            const int rowoff = q * 16;
            unsigned mbx = mb0 + 8u * q;
            unsigned bytes = (q == 4) ? (unsigned)SBBYTES : (unsigned)SABYTES;
            const CUtensorMap* tm = (q == 4) ? &tmapB : &tmapA;
            asm volatile("mbarrier.arrive.expect_tx.shared.b64 _, [%0], %1;"
                         :: "r"(mbx), "r"(bytes) : "memory");
            asm volatile(
                "cp.async.bulk.tensor.3d.shared::cta.global.tile"
                ".mbarrier::complete_tx::bytes [%0], [%1, {%2, %3, %4}], [%5];"
                :: "r"(smem_u32(&tile[rowoff][0])), "l"(tm),
                   "r"(tileX - 4), "r"(tileY - 3 + rowoff), "r"(img), "r"(mbx)
                : "memory");
        }
    }

    // Warp w streams rows w*16 .. w*16+21 -> needs slices w and w+1.
    mbar_wait(mb0 + 8u * wid,       0);
    mbar_wait(mb0 + 8u * (wid + 1), 0);

    compute_tile(tile, w1p, w2p, w3p, w4p, op, tileX, tileY);
}

// ---- fallback kernel (TMA encode unavailable) ----
__global__ void __launch_bounds__(NTH, 5)
mgdf_ldg_kernel(const float* __restrict__ s,
                const float* __restrict__ w1p, const float* __restrict__ w2p,
                const float* __restrict__ w3p, const float* __restrict__ w4p,
                float* __restrict__ out)
{
    __shared__ __align__(16) float tile[SH][SW];

    const int img = blockIdx.z;
    const size_t base = (size_t)img * (IMG * IMG);
    const float* sp = s + base;
    float* op = out + base;
    const int tileX = blockIdx.x * TX;
    const int tileY = blockIdx.y * TY;
    const int tid = threadIdx.x;

    #pragma unroll
    for (int idx = tid; idx < SH * NF4; idx += NTH) {
        int r = idx / NF4;
        int c4 = idx - r * NF4;
        int gy = tileY - 3 + r;
        int gx = tileX - 4 + c4 * 4;
        float4 v = make_float4(0.f, 0.f, 0.f, 0.f);
        if ((unsigned)gy < (unsigned)IMG && (unsigned)gx < (unsigned)IMG)
            v = *reinterpret_cast<const float4*>(sp + gy * IMG + gx);
        *reinterpret_cast<float4*>(&tile[r][c4 * 4]) = v;
    }
    __syncthreads();

    compute_tile(tile, w1p, w2p, w3p, w4p, op, tileX, tileY);
}

typedef CUresult (*PFN_tmapEncode)(
    CUtensorMap*, CUtensorMapDataType, cuuint32_t, void*,
    const cuuint64_t*, const cuuint64_t*, const cuuint32_t*, const cuuint32_t*,
    CUtensorMapInterleave, CUtensorMapSwizzle, CUtensorMapL2promotion,
    CUtensorMapFloatOOBfill);

extern "C" void kernel_launch(void* const* d_in, const int* in_sizes, int n_in,
                              void* d_out, int out_size)
{
    const float* s  = (const float*)d_in[0];
    const float* w1 = (const float*)d_in[1];
    const float* w2 = (const float*)d_in[2];
    const float* w3 = (const float*)d_in[3];
    const float* w4 = (const float*)d_in[4];
    float* out = (float*)d_out;

    const int n_img = in_sizes[0] / (IMG * IMG);       // 192
    dim3 grid(IMG / TX, IMG / TY, n_img);              // (4, 8, 192) = 6144

    static PFN_tmapEncode pfn = nullptr;
    static bool resolved = false;
    if (!resolved) {
        void* fp = nullptr;
        cudaDriverEntryPointQueryResult qr = cudaDriverEntryPointSymbolNotFound;
        if (cudaGetDriverEntryPointByVersion("cuTensorMapEncodeTiled", &fp, 12000,
                                             cudaEnableDefault, &qr) == cudaSuccess &&
            qr == cudaDriverEntryPointSuccess)
            pfn = (PFN_tmapEncode)fp;
        resolved = true;
    }

    CUtensorMap tmapA, tmapB;
    bool use_tma = false;
    if (pfn) {
        cuuint64_t dims[3]    = {IMG, IMG, (cuuint64_t)n_img};
        cuuint64_t strides[2] = {IMG * 4ull, (cuuint64_t)IMG * IMG * 4ull};
        cuuint32_t boxA[3]    = {SW, SAROWS, 1};
        cuuint32_t boxB[3]    = {SW, SBROWS, 1};
        cuuint32_t estr[3]    = {1, 1, 1};
        bool okA = (pfn(&tmapA, CU_TENSOR_MAP_DATA_TYPE_FLOAT32, 3, (void*)s,
                        dims, strides, boxA, estr,
                        CU_TENSOR_MAP_INTERLEAVE_NONE, CU_TENSOR_MAP_SWIZZLE_NONE,
                        CU_TENSOR_MAP_L2_PROMOTION_L2_128B,
                        CU_TENSOR_MAP_FLOAT_OOB_FILL_NONE) == CUDA_SUCCESS);
        bool okB = (pfn(&tmapB, CU_TENSOR_MAP_DATA_TYPE_FLOAT32, 3, (void*)s,
                        dims, strides, boxB, estr,
                        CU_TENSOR_MAP_INTERLEAVE_NONE, CU_TENSOR_MAP_SWIZZLE_NONE,
                        CU_TENSOR_MAP_L2_PROMOTION_L2_128B,
                        CU_TENSOR_MAP_FLOAT_OOB_FILL_NONE) == CUDA_SUCCESS);
        use_tma = okA && okB;
    }

    if (use_tma)
        mgdf_tma_kernel<<<grid, NTH>>>(tmapA, tmapB, w1, w2, w3, w4, out);
    else
        mgdf_ldg_kernel<<<grid, NTH>>>(s, w1, w2, w3, w4, out);
}